// round 5
// baseline (speedup 1.0000x reference)
#include <cuda_runtime.h>

#define B_  65536
#define T_  28
#define IN_ 28
#define HD_ 28
#define NC_ 10

typedef unsigned long long ull;

__device__ __forceinline__ ull pack2(float lo, float hi) {
    ull r; asm("mov.b64 %0, {%1, %2};" : "=l"(r) : "f"(lo), "f"(hi)); return r;
}
__device__ __forceinline__ void fma2(ull& acc, ull a, ull b) {
    asm("fma.rn.f32x2 %0, %1, %2, %0;" : "+l"(acc) : "l"(a), "l"(b));
}
__device__ __forceinline__ float hadd2(ull v) {
    float lo, hi; asm("mov.b64 {%0, %1}, %2;" : "=f"(lo), "=f"(hi) : "l"(v));
    return lo + hi;
}
__device__ __forceinline__ float tanh_a(float v) {
    float r; asm("tanh.approx.f32 %0, %1;" : "=f"(r) : "f"(v)); return r;
}
__device__ __forceinline__ float sigm(float v) {
    return fmaf(0.5f, tanh_a(0.5f * v), 0.5f);
}
__device__ __forceinline__ void barpair(int id) {
    asm volatile("bar.sync %0, %1;" :: "r"(id), "r"(64) : "memory");
}

// encoder step: half-warp-split dot, gate-parallel, branchless activation (R4)
__device__ __forceinline__ void enc_step(const ull (&ew)[8], float ebv_eff, int xoff,
                                         float eA, float eB, float eC, int u,
                                         const float* xrow,
                                         ull& he01, ull& he23, float& ce)
{
    const ulonglong2* xp = (const ulonglong2*)xrow + xoff;
    ulonglong2 v0 = xp[0], v1 = xp[1], v2 = xp[2], v3 = xp[3];
    ull o6 = xoff ? he01 : v3.x;
    ull o7 = xoff ? he23 : v3.y;
    ull acc0 = pack2(ebv_eff, 0.f);
    ull acc1 = pack2(0.f, 0.f);
    fma2(acc0, ew[0], v0.x); fma2(acc1, ew[1], v0.y);
    fma2(acc0, ew[2], v1.x); fma2(acc1, ew[3], v1.y);
    fma2(acc0, ew[4], v2.x); fma2(acc1, ew[5], v2.y);
    fma2(acc0, ew[6], o6);   fma2(acc1, ew[7], o7);
    float s = hadd2(acc0) + hadd2(acc1);
    s += __shfl_xor_sync(0xffffffffu, s, 16, 32);
    float gact = fmaf(eA, tanh_a(eB * s), eC);
    float ai = __shfl_sync(0xffffffffu, gact, u,      32);
    float af = __shfl_sync(0xffffffffu, gact, u + 4,  32);
    float ag = __shfl_sync(0xffffffffu, gact, u + 8,  32);
    float ao = __shfl_sync(0xffffffffu, gact, u + 12, 32);
    float cen = af * ce + ai * ag;
    ce = cen;
    float hn = ao * tanh_a(cen);
    he01 = pack2(__shfl_sync(0xffffffffu, hn, 0, 32),
                 __shfl_sync(0xffffffffu, hn, 1, 32));
    he23 = pack2(__shfl_sync(0xffffffffu, hn, 2, 32),
                 __shfl_sync(0xffffffffu, hn, 3, 32));
}

// block = 256 threads = 8 warps = 4 samples (2 warps per sample)
__global__ void __launch_bounds__(256, 2)
ae_lstm_kernel(const float* __restrict__ x,
               const float* __restrict__ eWih, const float* __restrict__ eWhh,
               const float* __restrict__ eb,
               const float* __restrict__ dWih, const float* __restrict__ dWhh,
               const float* __restrict__ db,
               const float* __restrict__ uW,  const float* __restrict__ ubv,
               float* __restrict__ out, float* __restrict__ pred)
{
    __shared__ float sU[NC_ * HD_ + NC_];
    __shared__ __align__(16) float hbuf[4][2][32];
    __shared__ __align__(16) float xbuf[4][2][32];

    for (int i = threadIdx.x; i < NC_ * HD_; i += blockDim.x) sU[i] = uW[i];
    for (int i = threadIdx.x; i < NC_;       i += blockDim.x) sU[NC_ * HD_ + i] = ubv[i];
    __syncthreads();

    const int lane  = threadIdx.x & 31;
    const int wid   = threadIdx.x >> 5;     // 0..7
    const int pair  = wid >> 1;             // 0..3 (sample within block)
    const int off   = (wid & 1) * 14;       // unit offset this warp covers
    const int b     = blockIdx.x * 4 + pair;
    const int barid = pair + 1;

    // ---------- decoder weights: lane owns 2 gate rows of one unit ----------
    // lanes 0-13: rows (i,f) of unit off+l ; lanes 14-27: rows (g,o) of unit off+l-14
    const int lc  = (lane < 28) ? lane : 27;
    const int uj  = off + ((lc < 14) ? lc : lc - 14);
    const int rowA = ((lc < 14) ? 0 : 56) + uj;      // i or g
    const int rowB = rowA + 28;                      // f or o
    ull wA[14], wB[14], wiA[2], wiB[2];
    float bAv, bBv;
    {
        const float4* rA = (const float4*)(dWhh + (size_t)rowA * HD_);
        const float4* rB = (const float4*)(dWhh + (size_t)rowB * HD_);
#pragma unroll
        for (int q = 0; q < 7; ++q) {
            float4 a = __ldg(rA + q), c = __ldg(rB + q);
            wA[2*q] = pack2(a.x, a.y); wA[2*q+1] = pack2(a.z, a.w);
            wB[2*q] = pack2(c.x, c.y); wB[2*q+1] = pack2(c.z, c.w);
        }
        float4 ua = __ldg((const float4*)(dWih + rowA * 4));
        float4 ub4 = __ldg((const float4*)(dWih + rowB * 4));
        wiA[0] = pack2(ua.x, ua.y);  wiA[1] = pack2(ua.z, ua.w);
        wiB[0] = pack2(ub4.x, ub4.y); wiB[1] = pack2(ub4.z, ub4.w);
        bAv = __ldg(db + rowA);
        bBv = __ldg(db + rowB);
    }
    // p0 activation: lanes<14 (i)-> sigm ; lanes>=14 (g)-> tanh. p1 always sigm.
    const bool  isg = (lc >= 14);
    const float dA = isg ? 1.0f : 0.5f;
    const float dB = isg ? 1.0f : 0.5f;
    const float dC = isg ? 0.0f : 0.5f;

    // ---------- encoder weights (half-warp split; both warps redundant) ----------
    const int r = lane & 15;
    const int u = lane & 3;
    const int xoff = (lane < 16) ? 0 : 4;
    ull   ew[8];
    float ebv_eff;
    {
        const float2* p = (const float2*)(eWih + (size_t)r * IN_);
        if (lane < 16) {
#pragma unroll
            for (int m = 0; m < 8; ++m) { float2 v = __ldg(p + m); ew[m] = pack2(v.x, v.y); }
            ebv_eff = __ldg(eb + r);
        } else {
#pragma unroll
            for (int m = 0; m < 6; ++m) { float2 v = __ldg(p + 8 + m); ew[m] = pack2(v.x, v.y); }
            const float2* ph = (const float2*)(eWhh + r * 4);
            float2 h0 = __ldg(ph), h1 = __ldg(ph + 1);
            ew[6] = pack2(h0.x, h0.y);
            ew[7] = pack2(h1.x, h1.y);
            ebv_eff = 0.f;
        }
    }
    const bool  eg = (r >= 8 && r < 12);
    const float eA = eg ? 1.0f : 0.5f;
    const float eB = eg ? 1.0f : 0.5f;
    const float eC = eg ? 0.0f : 0.5f;

    // ---------- state ----------
    ull   he01 = 0ull, he23 = 0ull;
    float cd = 0.f, ce = 0.f;
    const int shsrc = (lane < 14) ? lane + 14 : lane;

    const float* xrow = x + (size_t)b * T_ * IN_;
    float*       ob   = out + (size_t)b * T_ * HD_;

    // ---------- prologue ----------
    if (off == 0 && lane < IN_) {
        xbuf[pair][0][lane] = __ldg(xrow + lane);
        xbuf[pair][1][lane] = __ldg(xrow + IN_ + lane);
        hbuf[pair][1][lane] = 0.f;
    }
    barpair(barid);
    enc_step(ew, ebv_eff, xoff, eA, eB, eC, u, xbuf[pair][0], he01, he23, ce);

    // ---------- main loop: body(t) = dec(t-1) || enc(t) ----------
#pragma unroll 1
    for (int t = 1; t < T_; ++t) {
        ull hp0 = he01, hp1 = he23;                 // he_{t-1}
        float xn = 0.f;
        if (off == 0 && t + 1 < T_ && lane < IN_)
            xn = __ldg(xrow + (t + 1) * IN_ + lane);

        // dec pre-activations (2 gate rows)
        const ulonglong2* hv = (const ulonglong2*)hbuf[pair][t & 1];
        ull a0 = pack2(bAv, 0.f);
        ull a1 = pack2(bBv, 0.f);
        fma2(a0, wiA[0], hp0); fma2(a0, wiA[1], hp1);
        fma2(a1, wiB[0], hp0); fma2(a1, wiB[1], hp1);
#pragma unroll
        for (int m = 0; m < 7; ++m) {
            ulonglong2 v = hv[m];
            fma2(a0, wA[2*m], v.x); fma2(a0, wA[2*m+1], v.y);
            fma2(a1, wB[2*m], v.x); fma2(a1, wB[2*m+1], v.y);
        }
        float p0 = hadd2(a0), p1 = hadd2(a1);

        // encoder (independent of dec tail; overlaps its stalls)
        enc_step(ew, ebv_eff, xoff, eA, eB, eC, u, xbuf[pair][t & 1], he01, he23, ce);

        // activations + intra-warp gate combine
        float g0 = fmaf(dA, tanh_a(dB * p0), dC);   // ai (l<14) / pg (l>=14)
        float g1 = sigm(p1);                        // af (l<14) / po (l>=14)
        float pg = __shfl_sync(0xffffffffu, g0, shsrc, 32);
        float po = __shfl_sync(0xffffffffu, g1, shsrc, 32);
        if (lane < 14) {
            cd = g1 * cd + g0 * pg;
            float h = po * tanh_a(cd);
            ob[(t - 1) * HD_ + uj]         = h;
            hbuf[pair][(t - 1) & 1][uj]    = h;
        }
        if (off == 0 && t + 1 < T_ && lane < IN_)
            xbuf[pair][(t + 1) & 1][lane] = xn;
        barpair(barid);
    }

    // ---------- epilogue: dec(27) ----------
    {
        const ulonglong2* hv = (const ulonglong2*)hbuf[pair][0];
        ull a0 = pack2(bAv, 0.f);
        ull a1 = pack2(bBv, 0.f);
        fma2(a0, wiA[0], he01); fma2(a0, wiA[1], he23);
        fma2(a1, wiB[0], he01); fma2(a1, wiB[1], he23);
#pragma unroll
        for (int m = 0; m < 7; ++m) {
            ulonglong2 v = hv[m];
            fma2(a0, wA[2*m], v.x); fma2(a0, wA[2*m+1], v.y);
            fma2(a1, wB[2*m], v.x); fma2(a1, wB[2*m+1], v.y);
        }
        float p0 = hadd2(a0), p1 = hadd2(a1);
        float g0 = fmaf(dA, tanh_a(dB * p0), dC);
        float g1 = sigm(p1);
        float pg = __shfl_sync(0xffffffffu, g0, shsrc, 32);
        float po = __shfl_sync(0xffffffffu, g1, shsrc, 32);
        if (lane < 14) {
            cd = g1 * cd + g0 * pg;
            float h = po * tanh_a(cd);
            ob[(T_ - 1) * HD_ + uj] = h;
            hbuf[pair][1][uj]       = h;
        }
        barpair(barid);
    }

    // ---------- classifier head + softmax (one warp per sample) ----------
    if (off == 0) {
        ull hd[14];
        const ulonglong2* hv = (const ulonglong2*)hbuf[pair][1];
#pragma unroll
        for (int m = 0; m < 7; ++m) { ulonglong2 v = hv[m]; hd[2*m] = v.x; hd[2*m+1] = v.y; }

        const int k = (lane < NC_) ? lane : (NC_ - 1);
        const ull* uwk = (const ull*)(sU + k * HD_);
        ull a = pack2(sU[NC_ * HD_ + k], 0.f);
#pragma unroll
        for (int m = 0; m < 14; ++m) fma2(a, uwk[m], hd[m]);
        float lg = hadd2(a);

        float lv = (lane < NC_) ? lg : -3.4e38f;
#pragma unroll
        for (int o2 = 8; o2 >= 1; o2 >>= 1)
            lv = fmaxf(lv, __shfl_xor_sync(0xffffffffu, lv, o2, 16));
        float e = (lane < NC_) ? __expf(lg - lv) : 0.f;
        float s = e;
#pragma unroll
        for (int o2 = 8; o2 >= 1; o2 >>= 1)
            s += __shfl_xor_sync(0xffffffffu, s, o2, 16);
        if (lane < NC_)
            pred[(size_t)b * NC_ + lane] = e * __fdividef(1.0f, s);
    }
}

extern "C" void kernel_launch(void* const* d_in, const int* in_sizes, int n_in,
                              void* d_out, int out_size)
{
    const float* x    = (const float*)d_in[0];
    const float* eWih = (const float*)d_in[1];
    const float* eWhh = (const float*)d_in[2];
    const float* eb   = (const float*)d_in[3];
    const float* dWih = (const float*)d_in[4];
    const float* dWhh = (const float*)d_in[5];
    const float* db   = (const float*)d_in[6];
    const float* uW   = (const float*)d_in[7];
    const float* ub   = (const float*)d_in[8];

    float* out  = (float*)d_out;                 // [B, T, 28]
    float* pred = out + (size_t)B_ * T_ * HD_;   // [1, B, 10]

    dim3 grid(B_ / 4), block(256);               // 2 warps per sample
    ae_lstm_kernel<<<grid, block>>>(x, eWih, eWhh, eb, dWih, dWhh, db, uW, ub,
                                    out, pred);
}

// round 6
// speedup vs baseline: 1.6294x; 1.6294x over previous
#include <cuda_runtime.h>

#define B_  65536
#define T_  28
#define IN_ 28
#define HD_ 28
#define NC_ 10

typedef unsigned long long ull;

__device__ __forceinline__ ull pack2(float lo, float hi) {
    ull r; asm("mov.b64 %0, {%1, %2};" : "=l"(r) : "f"(lo), "f"(hi)); return r;
}
__device__ __forceinline__ void fma2(ull& acc, ull a, ull b) {
    asm("fma.rn.f32x2 %0, %1, %2, %0;" : "+l"(acc) : "l"(a), "l"(b));
}
__device__ __forceinline__ float hadd2(ull v) {
    float lo, hi; asm("mov.b64 {%0, %1}, %2;" : "=f"(lo), "=f"(hi) : "l"(v));
    return lo + hi;
}
__device__ __forceinline__ float tanh_a(float v) {
    float r; asm("tanh.approx.f32 %0, %1;" : "=f"(r) : "f"(v)); return r;
}
__device__ __forceinline__ float sigm(float v) {
    return fmaf(0.5f, tanh_a(0.5f * v), 0.5f);
}

// encoder step for one sample: half-warp-split dot, gate-parallel (R4)
__device__ __forceinline__ void enc_step(const ull (&ew)[8], float ebv_eff, int xoff,
                                         float eA, float eB, float eC, int u,
                                         const float* xrow,
                                         ull& he01, ull& he23, float& ce)
{
    const ulonglong2* xp = (const ulonglong2*)xrow + xoff;
    ulonglong2 v0 = xp[0], v1 = xp[1], v2 = xp[2], v3 = xp[3];
    ull o6 = xoff ? he01 : v3.x;
    ull o7 = xoff ? he23 : v3.y;
    ull acc0 = pack2(ebv_eff, 0.f);
    ull acc1 = pack2(0.f, 0.f);
    fma2(acc0, ew[0], v0.x); fma2(acc1, ew[1], v0.y);
    fma2(acc0, ew[2], v1.x); fma2(acc1, ew[3], v1.y);
    fma2(acc0, ew[4], v2.x); fma2(acc1, ew[5], v2.y);
    fma2(acc0, ew[6], o6);   fma2(acc1, ew[7], o7);
    float s = hadd2(acc0) + hadd2(acc1);
    s += __shfl_xor_sync(0xffffffffu, s, 16, 32);
    float gact = fmaf(eA, tanh_a(eB * s), eC);
    float ai = __shfl_sync(0xffffffffu, gact, u,      32);
    float af = __shfl_sync(0xffffffffu, gact, u + 4,  32);
    float ag = __shfl_sync(0xffffffffu, gact, u + 8,  32);
    float ao = __shfl_sync(0xffffffffu, gact, u + 12, 32);
    float cen = af * ce + ai * ag;
    ce = cen;
    float hn = ao * tanh_a(cen);
    he01 = pack2(__shfl_sync(0xffffffffu, hn, 0, 32),
                 __shfl_sync(0xffffffffu, hn, 1, 32));
    he23 = pack2(__shfl_sync(0xffffffffu, hn, 2, 32),
                 __shfl_sync(0xffffffffu, hn, 3, 32));
}

// block = 128 threads = 4 warps = 8 samples (2 samples per warp, interleaved)
__global__ void __launch_bounds__(128, 2)
ae_lstm_kernel(const float* __restrict__ x,
               const float* __restrict__ eWih, const float* __restrict__ eWhh,
               const float* __restrict__ eb,
               const float* __restrict__ dWih, const float* __restrict__ dWhh,
               const float* __restrict__ db,
               const float* __restrict__ uW,  const float* __restrict__ ubv,
               float* __restrict__ out, float* __restrict__ pred)
{
    __shared__ float sU[NC_ * HD_ + NC_];
    __shared__ __align__(16) float hbuf[4][2][2][32];   // [warp][sample][phase][lane]
    __shared__ __align__(16) float xbuf[4][2][2][32];

    for (int i = threadIdx.x; i < NC_ * HD_; i += blockDim.x) sU[i] = uW[i];
    for (int i = threadIdx.x; i < NC_;       i += blockDim.x) sU[NC_ * HD_ + i] = ubv[i];
    __syncthreads();

    const int lane = threadIdx.x & 31;
    const int w    = threadIdx.x >> 5;
    const int b0   = blockIdx.x * 8 + w * 2;   // sample A
    const int b1   = b0 + 1;                   // sample B

    // ---------- decoder weights -> registers (lane j owns unit j; clamp) ----------
    const int j = (lane < HD_) ? lane : (HD_ - 1);
    ull   dwhh[4][14];
    ull   dwih[4][2];
    float dbv[4];
#pragma unroll
    for (int g = 0; g < 4; ++g) {
        const float4* r4 = (const float4*)(dWhh + (size_t)(g * HD_ + j) * HD_);
#pragma unroll
        for (int q = 0; q < 7; ++q) {
            float4 v = __ldg(r4 + q);
            dwhh[g][2 * q]     = pack2(v.x, v.y);
            dwhh[g][2 * q + 1] = pack2(v.z, v.w);
        }
        float4 u4 = __ldg((const float4*)(dWih + (g * HD_ + j) * 4));
        dwih[g][0] = pack2(u4.x, u4.y);
        dwih[g][1] = pack2(u4.z, u4.w);
        dbv[g] = __ldg(db + g * HD_ + j);
    }

    // ---------- encoder weights (half-warp split) ----------
    const int r = lane & 15;
    const int u = lane & 3;
    const int xoff = (lane < 16) ? 0 : 4;
    ull   ew[8];
    float ebv_eff;
    {
        const float2* p = (const float2*)(eWih + (size_t)r * IN_);
        if (lane < 16) {
#pragma unroll
            for (int m = 0; m < 8; ++m) { float2 v = __ldg(p + m); ew[m] = pack2(v.x, v.y); }
            ebv_eff = __ldg(eb + r);
        } else {
#pragma unroll
            for (int m = 0; m < 6; ++m) { float2 v = __ldg(p + 8 + m); ew[m] = pack2(v.x, v.y); }
            const float2* ph = (const float2*)(eWhh + r * 4);
            float2 h0 = __ldg(ph), h1 = __ldg(ph + 1);
            ew[6] = pack2(h0.x, h0.y);
            ew[7] = pack2(h1.x, h1.y);
            ebv_eff = 0.f;
        }
    }
    const bool  eg = (r >= 8 && r < 12);
    const float eA = eg ? 1.0f : 0.5f;
    const float eB = eg ? 1.0f : 0.5f;
    const float eC = eg ? 0.0f : 0.5f;

    // ---------- state (dual) ----------
    ull   heA01 = 0ull, heA23 = 0ull, heB01 = 0ull, heB23 = 0ull;
    float cdA = 0.f, cdB = 0.f, ceA = 0.f, ceB = 0.f;

    const float* xrowA = x + (size_t)b0 * T_ * IN_;
    const float* xrowB = x + (size_t)b1 * T_ * IN_;
    float*       obA   = out + (size_t)b0 * T_ * HD_;
    float*       obB   = out + (size_t)b1 * T_ * HD_;

    // ---------- prologue ----------
    if (lane < IN_) {
        xbuf[w][0][0][lane] = __ldg(xrowA + lane);
        xbuf[w][0][1][lane] = __ldg(xrowA + IN_ + lane);
        xbuf[w][1][0][lane] = __ldg(xrowB + lane);
        xbuf[w][1][1][lane] = __ldg(xrowB + IN_ + lane);
        hbuf[w][0][1][lane] = 0.f;
        hbuf[w][1][1][lane] = 0.f;
    }
    __syncwarp();
    enc_step(ew, ebv_eff, xoff, eA, eB, eC, u, xbuf[w][0][0], heA01, heA23, ceA);
    enc_step(ew, ebv_eff, xoff, eA, eB, eC, u, xbuf[w][1][0], heB01, heB23, ceB);

    // ---------- main loop: body(t) = dec(t-1){A,B} || enc(t){A,B} ----------
#pragma unroll 1
    for (int t = 1; t < T_; ++t) {
        ull hpA0 = heA01, hpA1 = heA23;
        ull hpB0 = heB01, hpB1 = heB23;
        float xnA = 0.f, xnB = 0.f;
        if (t + 1 < T_ && lane < IN_) {
            xnA = __ldg(xrowA + (t + 1) * IN_ + lane);
            xnB = __ldg(xrowB + (t + 1) * IN_ + lane);
        }

        // ---- dual decoder pre-activations (shared weight regs) ----
        const ulonglong2* hvA = (const ulonglong2*)hbuf[w][0][t & 1];
        const ulonglong2* hvB = (const ulonglong2*)hbuf[w][1][t & 1];
        ull aA0 = pack2(dbv[0], 0.f), aB0 = aA0;
        ull aA1 = pack2(dbv[1], 0.f), aB1 = aA1;
        ull aA2 = pack2(dbv[2], 0.f), aB2 = aA2;
        ull aA3 = pack2(dbv[3], 0.f), aB3 = aA3;
        fma2(aA0, dwih[0][0], hpA0); fma2(aB0, dwih[0][0], hpB0);
        fma2(aA0, dwih[0][1], hpA1); fma2(aB0, dwih[0][1], hpB1);
        fma2(aA1, dwih[1][0], hpA0); fma2(aB1, dwih[1][0], hpB0);
        fma2(aA1, dwih[1][1], hpA1); fma2(aB1, dwih[1][1], hpB1);
        fma2(aA2, dwih[2][0], hpA0); fma2(aB2, dwih[2][0], hpB0);
        fma2(aA2, dwih[2][1], hpA1); fma2(aB2, dwih[2][1], hpB1);
        fma2(aA3, dwih[3][0], hpA0); fma2(aB3, dwih[3][0], hpB0);
        fma2(aA3, dwih[3][1], hpA1); fma2(aB3, dwih[3][1], hpB1);
#pragma unroll
        for (int m = 0; m < 7; ++m) {
            ulonglong2 vA = hvA[m];
            ulonglong2 vB = hvB[m];
            fma2(aA0, dwhh[0][2*m], vA.x); fma2(aB0, dwhh[0][2*m], vB.x);
            fma2(aA0, dwhh[0][2*m+1], vA.y); fma2(aB0, dwhh[0][2*m+1], vB.y);
            fma2(aA1, dwhh[1][2*m], vA.x); fma2(aB1, dwhh[1][2*m], vB.x);
            fma2(aA1, dwhh[1][2*m+1], vA.y); fma2(aB1, dwhh[1][2*m+1], vB.y);
            fma2(aA2, dwhh[2][2*m], vA.x); fma2(aB2, dwhh[2][2*m], vB.x);
            fma2(aA2, dwhh[2][2*m+1], vA.y); fma2(aB2, dwhh[2][2*m+1], vB.y);
            fma2(aA3, dwhh[3][2*m], vA.x); fma2(aB3, dwhh[3][2*m], vB.x);
            fma2(aA3, dwhh[3][2*m+1], vA.y); fma2(aB3, dwhh[3][2*m+1], vB.y);
        }

        // ---- dual encoder (independent; fills dec stall slots) ----
        enc_step(ew, ebv_eff, xoff, eA, eB, eC, u, xbuf[w][0][t & 1], heA01, heA23, ceA);
        enc_step(ew, ebv_eff, xoff, eA, eB, eC, u, xbuf[w][1][t & 1], heB01, heB23, ceB);

        // ---- dual decoder activations ----
        float giA = sigm(hadd2(aA0)), gfA = sigm(hadd2(aA1));
        float ggA = tanh_a(hadd2(aA2)), goA = sigm(hadd2(aA3));
        float giB = sigm(hadd2(aB0)), gfB = sigm(hadd2(aB1));
        float ggB = tanh_a(hadd2(aB2)), goB = sigm(hadd2(aB3));
        cdA = gfA * cdA + giA * ggA;
        cdB = gfB * cdB + giB * ggB;
        float hA = goA * tanh_a(cdA);
        float hB = goB * tanh_a(cdB);

        if (lane < HD_) {
            obA[(t - 1) * HD_ + lane] = hA;
            obB[(t - 1) * HD_ + lane] = hB;
            hbuf[w][0][(t - 1) & 1][lane] = hA;
            hbuf[w][1][(t - 1) & 1][lane] = hB;
            if (t + 1 < T_) {
                xbuf[w][0][(t + 1) & 1][lane] = xnA;
                xbuf[w][1][(t + 1) & 1][lane] = xnB;
            }
        }
        __syncwarp();
    }

    // ---------- epilogue: dec(27) dual ----------
    {
        const ulonglong2* hvA = (const ulonglong2*)hbuf[w][0][0];
        const ulonglong2* hvB = (const ulonglong2*)hbuf[w][1][0];
        ull aA0 = pack2(dbv[0], 0.f), aB0 = aA0;
        ull aA1 = pack2(dbv[1], 0.f), aB1 = aA1;
        ull aA2 = pack2(dbv[2], 0.f), aB2 = aA2;
        ull aA3 = pack2(dbv[3], 0.f), aB3 = aA3;
        fma2(aA0, dwih[0][0], heA01); fma2(aB0, dwih[0][0], heB01);
        fma2(aA0, dwih[0][1], heA23); fma2(aB0, dwih[0][1], heB23);
        fma2(aA1, dwih[1][0], heA01); fma2(aB1, dwih[1][0], heB01);
        fma2(aA1, dwih[1][1], heA23); fma2(aB1, dwih[1][1], heB23);
        fma2(aA2, dwih[2][0], heA01); fma2(aB2, dwih[2][0], heB01);
        fma2(aA2, dwih[2][1], heA23); fma2(aB2, dwih[2][1], heB23);
        fma2(aA3, dwih[3][0], heA01); fma2(aB3, dwih[3][0], heB01);
        fma2(aA3, dwih[3][1], heA23); fma2(aB3, dwih[3][1], heB23);
#pragma unroll
        for (int m = 0; m < 7; ++m) {
            ulonglong2 vA = hvA[m];
            ulonglong2 vB = hvB[m];
            fma2(aA0, dwhh[0][2*m], vA.x); fma2(aB0, dwhh[0][2*m], vB.x);
            fma2(aA0, dwhh[0][2*m+1], vA.y); fma2(aB0, dwhh[0][2*m+1], vB.y);
            fma2(aA1, dwhh[1][2*m], vA.x); fma2(aB1, dwhh[1][2*m], vB.x);
            fma2(aA1, dwhh[1][2*m+1], vA.y); fma2(aB1, dwhh[1][2*m+1], vB.y);
            fma2(aA2, dwhh[2][2*m], vA.x); fma2(aB2, dwhh[2][2*m], vB.x);
            fma2(aA2, dwhh[2][2*m+1], vA.y); fma2(aB2, dwhh[2][2*m+1], vB.y);
            fma2(aA3, dwhh[3][2*m], vA.x); fma2(aB3, dwhh[3][2*m], vB.x);
            fma2(aA3, dwhh[3][2*m+1], vA.y); fma2(aB3, dwhh[3][2*m+1], vB.y);
        }
        float giA = sigm(hadd2(aA0)), gfA = sigm(hadd2(aA1));
        float ggA = tanh_a(hadd2(aA2)), goA = sigm(hadd2(aA3));
        float giB = sigm(hadd2(aB0)), gfB = sigm(hadd2(aB1));
        float ggB = tanh_a(hadd2(aB2)), goB = sigm(hadd2(aB3));
        cdA = gfA * cdA + giA * ggA;
        cdB = gfB * cdB + giB * ggB;
        float hA = goA * tanh_a(cdA);
        float hB = goB * tanh_a(cdB);
        if (lane < HD_) {
            obA[(T_ - 1) * HD_ + lane] = hA;
            obB[(T_ - 1) * HD_ + lane] = hB;
            hbuf[w][0][1][lane] = hA;
            hbuf[w][1][1][lane] = hB;
        }
        __syncwarp();
    }

    // ---------- classifier head + softmax (both samples) ----------
#pragma unroll
    for (int s2 = 0; s2 < 2; ++s2) {
        const int bb = b0 + s2;
        ull hd[14];
        const ulonglong2* hv = (const ulonglong2*)hbuf[w][s2][1];
#pragma unroll
        for (int m = 0; m < 7; ++m) { ulonglong2 v = hv[m]; hd[2*m] = v.x; hd[2*m+1] = v.y; }

        const int k = (lane < NC_) ? lane : (NC_ - 1);
        const ull* uwk = (const ull*)(sU + k * HD_);
        ull a = pack2(sU[NC_ * HD_ + k], 0.f);
#pragma unroll
        for (int m = 0; m < 14; ++m) fma2(a, uwk[m], hd[m]);
        float lg = hadd2(a);

        float lv = (lane < NC_) ? lg : -3.4e38f;
#pragma unroll
        for (int o2 = 8; o2 >= 1; o2 >>= 1)
            lv = fmaxf(lv, __shfl_xor_sync(0xffffffffu, lv, o2, 16));
        float e = (lane < NC_) ? __expf(lg - lv) : 0.f;
        float sum = e;
#pragma unroll
        for (int o2 = 8; o2 >= 1; o2 >>= 1)
            sum += __shfl_xor_sync(0xffffffffu, sum, o2, 16);
        if (lane < NC_)
            pred[(size_t)bb * NC_ + lane] = e * __fdividef(1.0f, sum);
    }
}

extern "C" void kernel_launch(void* const* d_in, const int* in_sizes, int n_in,
                              void* d_out, int out_size)
{
    const float* x    = (const float*)d_in[0];
    const float* eWih = (const float*)d_in[1];
    const float* eWhh = (const float*)d_in[2];
    const float* eb   = (const float*)d_in[3];
    const float* dWih = (const float*)d_in[4];
    const float* dWhh = (const float*)d_in[5];
    const float* db   = (const float*)d_in[6];
    const float* uW   = (const float*)d_in[7];
    const float* ub   = (const float*)d_in[8];

    float* out  = (float*)d_out;                 // [B, T, 28]
    float* pred = out + (size_t)B_ * T_ * HD_;   // [1, B, 10]

    dim3 grid(B_ / 8), block(128);               // 2 samples per warp
    ae_lstm_kernel<<<grid, block>>>(x, eWih, eWhh, eb, dWih, dWhh, db, uW, ub,
                                    out, pred);
}

// round 7
// speedup vs baseline: 1.7914x; 1.0995x over previous
#include <cuda_runtime.h>

#define B_  65536
#define T_  28
#define IN_ 28
#define HD_ 28
#define NC_ 10
#define NS  3          // samples per warp

typedef unsigned long long ull;

__device__ __forceinline__ ull pack2(float lo, float hi) {
    ull r; asm("mov.b64 %0, {%1, %2};" : "=l"(r) : "f"(lo), "f"(hi)); return r;
}
__device__ __forceinline__ void fma2(ull& acc, ull a, ull b) {
    asm("fma.rn.f32x2 %0, %1, %2, %0;" : "+l"(acc) : "l"(a), "l"(b));
}
__device__ __forceinline__ float hadd2(ull v) {
    float lo, hi; asm("mov.b64 {%0, %1}, %2;" : "=f"(lo), "=f"(hi) : "l"(v));
    return lo + hi;
}
__device__ __forceinline__ float tanh_a(float v) {
    float r; asm("tanh.approx.f32 %0, %1;" : "=f"(r) : "f"(v)); return r;
}
__device__ __forceinline__ float sigm(float v) {
    return fmaf(0.5f, tanh_a(0.5f * v), 0.5f);
}

// encoder step for one sample: half-warp-split dot, gate-parallel
__device__ __forceinline__ void enc_step(const ull (&ew)[8], float ebv_eff, int xoff,
                                         float eA, float eB, float eC, int u,
                                         const float* xrow,
                                         ull& he01, ull& he23, float& ce)
{
    const ulonglong2* xp = (const ulonglong2*)xrow + xoff;
    ulonglong2 v0 = xp[0], v1 = xp[1], v2 = xp[2], v3 = xp[3];
    ull o6 = xoff ? he01 : v3.x;
    ull o7 = xoff ? he23 : v3.y;
    ull acc0 = pack2(ebv_eff, 0.f);
    ull acc1 = pack2(0.f, 0.f);
    fma2(acc0, ew[0], v0.x); fma2(acc1, ew[1], v0.y);
    fma2(acc0, ew[2], v1.x); fma2(acc1, ew[3], v1.y);
    fma2(acc0, ew[4], v2.x); fma2(acc1, ew[5], v2.y);
    fma2(acc0, ew[6], o6);   fma2(acc1, ew[7], o7);
    float s = hadd2(acc0) + hadd2(acc1);
    s += __shfl_xor_sync(0xffffffffu, s, 16, 32);
    float gact = fmaf(eA, tanh_a(eB * s), eC);
    float ai = __shfl_sync(0xffffffffu, gact, u,      32);
    float af = __shfl_sync(0xffffffffu, gact, u + 4,  32);
    float ag = __shfl_sync(0xffffffffu, gact, u + 8,  32);
    float ao = __shfl_sync(0xffffffffu, gact, u + 12, 32);
    float cen = af * ce + ai * ag;
    ce = cen;
    float hn = ao * tanh_a(cen);
    he01 = pack2(__shfl_sync(0xffffffffu, hn, 0, 32),
                 __shfl_sync(0xffffffffu, hn, 1, 32));
    he23 = pack2(__shfl_sync(0xffffffffu, hn, 2, 32),
                 __shfl_sync(0xffffffffu, hn, 3, 32));
}

// block = 128 threads = 4 warps = 12 samples (3 per warp, interleaved ILP)
__global__ void __launch_bounds__(128, 2)
ae_lstm_kernel(const float* __restrict__ x,
               const float* __restrict__ eWih, const float* __restrict__ eWhh,
               const float* __restrict__ eb,
               const float* __restrict__ dWih, const float* __restrict__ dWhh,
               const float* __restrict__ db,
               const float* __restrict__ uW,  const float* __restrict__ ubv,
               float* __restrict__ out, float* __restrict__ pred)
{
    __shared__ float sU[NC_ * HD_ + NC_];
    __shared__ __align__(16) float hbuf[4][NS][2][32];
    __shared__ __align__(16) float xbuf[4][NS][2][32];

    for (int i = threadIdx.x; i < NC_ * HD_; i += blockDim.x) sU[i] = uW[i];
    for (int i = threadIdx.x; i < NC_;       i += blockDim.x) sU[NC_ * HD_ + i] = ubv[i];
    __syncthreads();

    const int lane = threadIdx.x & 31;
    const int w    = threadIdx.x >> 5;
    const int base = blockIdx.x * (4 * NS) + w * NS;

    int  bs[NS];
    bool vs[NS];
#pragma unroll
    for (int s = 0; s < NS; ++s) {
        int bb = base + s;
        vs[s] = (bb < B_);
        bs[s] = vs[s] ? bb : (B_ - 1);
    }

    // ---------- decoder weights -> registers (lane j owns unit j; clamp) ----------
    const int j = (lane < HD_) ? lane : (HD_ - 1);
    ull   dwhh[4][14];
    ull   dwih[4][2];
    float dbv[4];
#pragma unroll
    for (int g = 0; g < 4; ++g) {
        const float4* r4 = (const float4*)(dWhh + (size_t)(g * HD_ + j) * HD_);
#pragma unroll
        for (int q = 0; q < 7; ++q) {
            float4 v = __ldg(r4 + q);
            dwhh[g][2 * q]     = pack2(v.x, v.y);
            dwhh[g][2 * q + 1] = pack2(v.z, v.w);
        }
        float4 u4 = __ldg((const float4*)(dWih + (g * HD_ + j) * 4));
        dwih[g][0] = pack2(u4.x, u4.y);
        dwih[g][1] = pack2(u4.z, u4.w);
        dbv[g] = __ldg(db + g * HD_ + j);
    }

    // ---------- encoder weights (half-warp split) ----------
    const int r = lane & 15;
    const int u = lane & 3;
    const int xoff = (lane < 16) ? 0 : 4;
    ull   ew[8];
    float ebv_eff;
    {
        const float2* p = (const float2*)(eWih + (size_t)r * IN_);
        if (lane < 16) {
#pragma unroll
            for (int m = 0; m < 8; ++m) { float2 v = __ldg(p + m); ew[m] = pack2(v.x, v.y); }
            ebv_eff = __ldg(eb + r);
        } else {
#pragma unroll
            for (int m = 0; m < 6; ++m) { float2 v = __ldg(p + 8 + m); ew[m] = pack2(v.x, v.y); }
            const float2* ph = (const float2*)(eWhh + r * 4);
            float2 h0 = __ldg(ph), h1 = __ldg(ph + 1);
            ew[6] = pack2(h0.x, h0.y);
            ew[7] = pack2(h1.x, h1.y);
            ebv_eff = 0.f;
        }
    }
    const bool  eg = (r >= 8 && r < 12);
    const float eA = eg ? 1.0f : 0.5f;
    const float eB = eg ? 1.0f : 0.5f;
    const float eC = eg ? 0.0f : 0.5f;

    // ---------- state ----------
    ull   he01[NS], he23[NS];
    float cd[NS], ce[NS];
    const float* xr[NS];
#pragma unroll
    for (int s = 0; s < NS; ++s) {
        he01[s] = 0ull; he23[s] = 0ull; cd[s] = 0.f; ce[s] = 0.f;
        xr[s] = x + (size_t)bs[s] * T_ * IN_;
    }

    // ---------- prologue ----------
    if (lane < IN_) {
#pragma unroll
        for (int s = 0; s < NS; ++s) {
            xbuf[w][s][0][lane] = __ldg(xr[s] + lane);
            xbuf[w][s][1][lane] = __ldg(xr[s] + IN_ + lane);
            hbuf[w][s][1][lane] = 0.f;
        }
    }
    __syncwarp();
#pragma unroll
    for (int s = 0; s < NS; ++s)
        enc_step(ew, ebv_eff, xoff, eA, eB, eC, u, xbuf[w][s][0], he01[s], he23[s], ce[s]);

    // ---------- unified loop: t in [1, T_]; body = dec(t-1) || enc(t) ----------
#pragma unroll 1
    for (int t = 1; t <= T_; ++t) {
        ull hp0[NS], hp1[NS];
#pragma unroll
        for (int s = 0; s < NS; ++s) { hp0[s] = he01[s]; hp1[s] = he23[s]; }

        float xn[NS];
#pragma unroll
        for (int s = 0; s < NS; ++s) xn[s] = 0.f;
        if (t + 1 < T_ && lane < IN_) {
#pragma unroll
            for (int s = 0; s < NS; ++s) xn[s] = __ldg(xr[s] + (t + 1) * IN_ + lane);
        }

        // ---- tri-sample decoder pre-activations (shared weight regs) ----
        ull a[NS][4];
#pragma unroll
        for (int s = 0; s < NS; ++s) {
#pragma unroll
            for (int g = 0; g < 4; ++g) a[s][g] = pack2(dbv[g], 0.f);
            fma2(a[s][0], dwih[0][0], hp0[s]); fma2(a[s][0], dwih[0][1], hp1[s]);
            fma2(a[s][1], dwih[1][0], hp0[s]); fma2(a[s][1], dwih[1][1], hp1[s]);
            fma2(a[s][2], dwih[2][0], hp0[s]); fma2(a[s][2], dwih[2][1], hp1[s]);
            fma2(a[s][3], dwih[3][0], hp0[s]); fma2(a[s][3], dwih[3][1], hp1[s]);
        }
        const int ph = t & 1;
#pragma unroll
        for (int m = 0; m < 7; ++m) {
#pragma unroll
            for (int s = 0; s < NS; ++s) {
                ulonglong2 v = ((const ulonglong2*)hbuf[w][s][ph])[m];
                fma2(a[s][0], dwhh[0][2*m], v.x); fma2(a[s][0], dwhh[0][2*m+1], v.y);
                fma2(a[s][1], dwhh[1][2*m], v.x); fma2(a[s][1], dwhh[1][2*m+1], v.y);
                fma2(a[s][2], dwhh[2][2*m], v.x); fma2(a[s][2], dwhh[2][2*m+1], v.y);
                fma2(a[s][3], dwhh[3][2*m], v.x); fma2(a[s][3], dwhh[3][2*m+1], v.y);
            }
        }

        // ---- encoders (skip on final iteration) ----
        if (t < T_) {
#pragma unroll
            for (int s = 0; s < NS; ++s)
                enc_step(ew, ebv_eff, xoff, eA, eB, eC, u, xbuf[w][s][ph],
                         he01[s], he23[s], ce[s]);
        }

        // ---- activations + stores ----
#pragma unroll
        for (int s = 0; s < NS; ++s) {
            float gi = sigm(hadd2(a[s][0]));
            float gf = sigm(hadd2(a[s][1]));
            float gg = tanh_a(hadd2(a[s][2]));
            float go = sigm(hadd2(a[s][3]));
            float c  = gf * cd[s] + gi * gg;
            cd[s] = c;
            float h  = go * tanh_a(c);
            if (lane < HD_) {
                if (vs[s]) out[(size_t)bs[s] * T_ * HD_ + (t - 1) * HD_ + lane] = h;
                hbuf[w][s][(t - 1) & 1][lane] = h;
                if (t + 1 < T_) xbuf[w][s][(t + 1) & 1][lane] = xn[s];
            }
        }
        __syncwarp();
    }

    // ---------- classifier head + softmax per sample ----------
#pragma unroll
    for (int s = 0; s < NS; ++s) {
        ull hd[14];
        const ulonglong2* hv = (const ulonglong2*)hbuf[w][s][1];
#pragma unroll
        for (int m = 0; m < 7; ++m) { ulonglong2 v = hv[m]; hd[2*m] = v.x; hd[2*m+1] = v.y; }

        const int k = (lane < NC_) ? lane : (NC_ - 1);
        const ull* uwk = (const ull*)(sU + k * HD_);
        ull acc = pack2(sU[NC_ * HD_ + k], 0.f);
#pragma unroll
        for (int m = 0; m < 14; ++m) fma2(acc, uwk[m], hd[m]);
        float lg = hadd2(acc);

        float lv = (lane < NC_) ? lg : -3.4e38f;
#pragma unroll
        for (int o2 = 8; o2 >= 1; o2 >>= 1)
            lv = fmaxf(lv, __shfl_xor_sync(0xffffffffu, lv, o2, 16));
        float e = (lane < NC_) ? __expf(lg - lv) : 0.f;
        float sum = e;
#pragma unroll
        for (int o2 = 8; o2 >= 1; o2 >>= 1)
            sum += __shfl_xor_sync(0xffffffffu, sum, o2, 16);
        if (lane < NC_ && vs[s])
            pred[(size_t)bs[s] * NC_ + lane] = e * __fdividef(1.0f, sum);
    }
}

extern "C" void kernel_launch(void* const* d_in, const int* in_sizes, int n_in,
                              void* d_out, int out_size)
{
    const float* x    = (const float*)d_in[0];
    const float* eWih = (const float*)d_in[1];
    const float* eWhh = (const float*)d_in[2];
    const float* eb   = (const float*)d_in[3];
    const float* dWih = (const float*)d_in[4];
    const float* dWhh = (const float*)d_in[5];
    const float* db   = (const float*)d_in[6];
    const float* uW   = (const float*)d_in[7];
    const float* ub   = (const float*)d_in[8];

    float* out  = (float*)d_out;                 // [B, T, 28]
    float* pred = out + (size_t)B_ * T_ * HD_;   // [1, B, 10]

    const int spb  = 4 * NS;                     // samples per block
    dim3 grid((B_ + spb - 1) / spb), block(128);
    ae_lstm_kernel<<<grid, block>>>(x, eWih, eWhh, eb, dWih, dWhh, db, uW, ub,
                                    out, pred);
}